// round 8
// baseline (speedup 1.0000x reference)
#include <cuda_runtime.h>
#include <math.h>

#define NN    68
#define TPB   128
#define TILE  32

typedef unsigned long long u64;

// Packed f32x2 ops (Blackwell) — only reachable via PTX.
__device__ __forceinline__ u64 ffma2(u64 a, u64 b, u64 c) {
    u64 d;
    asm("fma.rn.f32x2 %0, %1, %2, %3;" : "=l"(d) : "l"(a), "l"(b), "l"(c));
    return d;
}
__device__ __forceinline__ u64 fadd2(u64 a, u64 b) {
    u64 d;
    asm("add.rn.f32x2 %0, %1, %2;" : "=l"(d) : "l"(a), "l"(b));
    return d;
}
__device__ __forceinline__ u64 fmul2(u64 a, u64 b) {
    u64 d;
    asm("mul.rn.f32x2 %0, %1, %2;" : "=l"(d) : "l"(a), "l"(b));
    return d;
}
__device__ __forceinline__ void unpk(u64 v, float &x, float &y) {
    asm("mov.b64 {%0, %1}, %2;" : "=f"(x), "=f"(y) : "l"(v));
}
__device__ __forceinline__ u64 pack2(float x, float y) {
    u64 v;
    asm("mov.b64 %0, {%1, %2};" : "=l"(v) : "f"(x), "f"(y));
    return v;
}
// MUFU fast paths (~1e-7 rel err; validated 1.3e-6 final over 200k steps).
__device__ __forceinline__ float ex2a(float x) {
    float y; asm("ex2.approx.f32 %0, %1;" : "=f"(y) : "f"(x)); return y;
}
__device__ __forceinline__ float rcpa(float x) {
    float y; asm("rcp.approx.f32 %0, %1;" : "=f"(y) : "f"(x)); return y;
}

__global__ __launch_bounds__(TPB, 1)
void nmm_kernel(const float* __restrict__ params,
                const float* __restrict__ C,
                const float* __restrict__ y0,
                float* __restrict__ out,
                int num_steps)
{
    // Interleaved E ring: einter[b][j] = {E_odd[j], E_even[j]} pairs.
    // Block k (steps 2k, 2k+1) READS einter[k&1] = {E_{2k-1}, E_{2k}} and
    // WRITES einter[(k&1)^1] = {E_{2k+1}, E_{2k+2}} — one barrier per block
    // orders every crossing (reads precede the BAR, next block's writes
    // follow it).
    __shared__ __align__(16) u64 einter[2][72];
    // Ping-pong output staging; pad 34 => 8B-aligned rows for STS.64 pairs,
    // flush reads stay conflict-free.
    __shared__ __align__(16) float outbuf[2][NN][TILE + 2];

    const int tid  = threadIdx.x;
    const int lane = tid & 31;
    const int wid  = tid >> 5;
    const int r    = tid;                 // row owned by this thread (r < 68)

    const float tau_e = params[0], tau_i = params[1];
    const float c1 = params[2], c2 = params[3], c3 = params[4], c4 = params[5];
    const float c5 = params[6], Pp = params[7], kE = params[8], kI = params[9];
    const float inv_te = 1.0f / tau_e;
    const float inv_ti = 1.0f / tau_i;

    const float LOG2E = 1.4426950408889634f;
    const float AE = 1.3f, THR_E = 4.0f;
    const float AI = 2.0f, THR_I = 3.7f;
    const float aeL = AE * LOG2E;
    const float aiL = AI * LOG2E;
    const float S0E = 1.0f / (1.0f + expf(AE * THR_E));
    const float S0I = 1.0f / (1.0f + expf(AI * THR_I));
    const float kconn = -aeL * c5;        // folded into coefficients below

    // Packed constants for {E, I}-lane pointwise math.
    const u64 kinvt2 = pack2(kE * inv_te, kI * inv_ti);
    const u64 ninvt2 = pack2(-inv_te, -inv_ti);
    const u64 cc2    = pack2(1.0f - inv_te, 1.0f - inv_ti);
    const u64 nS02   = pack2(-S0E, -S0I);
    const u64 m2     = pack2(-aeL * c1, -aiL * c3);   // {mEc1, mIc3}
    const u64 p2     = pack2( aeL * c2,  aiL * c4);   // {pEc2, pIc4}
    const u64 c02    = pack2(aeL * (THR_E - Pp), aiL * THR_I);

    u64 EI = 0ull;                        // {E, I} state for this row
    u64 cw[68];                           // {kconn*C[r][c], same} per column

    if (r < NN) {
        const float E0 = y0[r];
        const float I0 = y0[NN + r];
        EI = pack2(E0, I0);
        einter[0][r] = pack2(E0, E0);     // {E_{-1}, E_0} = {E0, E0}
        #pragma unroll
        for (int c = 0; c < NN; c++) {
            const float v = kconn * C[r * NN + c];
            cw[c] = pack2(v, v);
        }
    }
    __syncthreads();

    // Warp-3 flush of one step's column window (17 rows x 4 windows/tile).
#define FLUSH_STEP(X)                                                          \
    {                                                                          \
        const int fk = (X) & 31;                                               \
        if (fk < 4 && (X) >= 32) {                                             \
            const int fb    = ((X) >> 5) - 1;                                  \
            const int ftile = fb & 1;                                          \
            const int fbase = fb << 5;                                         \
            _Pragma("unroll")                                                  \
            for (int i = 0; i < 17; i++) {                                     \
                const int row = fk * 17 + i;                                   \
                out[row * num_steps + fbase + lane] = outbuf[ftile][row][lane];\
            }                                                                  \
        }                                                                      \
    }

    // ---- one block = 2 Euler steps (S = 2k even), ONE barrier ----
    // CUR = k & 1 (compile-time in the main loop).
#define BLOCK(CUR, S)                                                          \
    {                                                                          \
        if (r < NN) {                                                          \
            /* pointwise-A (packed {E,I}) from state at iteration S */         \
            const u64 g2a = ffma2(EI, ninvt2, kinvt2);                         \
            const u64 h2a = ffma2(g2a, nS02, fmul2(EI, cc2));                  \
            float Ea, Ia;                                                      \
            unpk(EI, Ea, Ia);                                                  \
            const u64 ba_a = ffma2(m2, pack2(Ea, Ea),                          \
                                   ffma2(p2, pack2(Ia, Ia), c02));             \
            float base_ea, argIa;                                              \
            unpk(ba_a, base_ea, argIa);                                        \
            const float sIa = rcpa(1.0f + ex2a(argIa));                        \
            /* ONE packed matvec stream: lane-pair {stepA, stepB} per col */   \
            const ulonglong2* eb =                                             \
                reinterpret_cast<const ulonglong2*>(einter[(CUR)]);            \
            u64 a0 = pack2(base_ea, 0.0f);  /* seed base_ea into A-half */     \
            u64 a1 = 0ull, a2 = 0ull, a3 = 0ull;                               \
            _Pragma("unroll")                                                  \
            for (int j = 0; j < 34; j++) {                                     \
                ulonglong2 e = eb[j];                                          \
                if (j & 1) {                                                   \
                    a2 = ffma2(cw[2 * j],     e.x, a2);                        \
                    a3 = ffma2(cw[2 * j + 1], e.y, a3);                        \
                } else {                                                       \
                    a0 = ffma2(cw[2 * j],     e.x, a0);                        \
                    a1 = ffma2(cw[2 * j + 1], e.y, a1);                        \
                }                                                              \
            }                                                                  \
            u64 sv = fadd2(fadd2(a0, a2), fadd2(a1, a3));                      \
            float argEa, connB;                                                \
            unpk(sv, argEa, connB);       /* both steps' dots, one reduce */   \
            /* tail-A */                                                       \
            const float sEa = rcpa(1.0f + ex2a(argEa));                        \
            const u64 EIa = ffma2(g2a, pack2(sEa, sIa), h2a);                  \
            float Ena, Ina;                                                    \
            unpk(EIa, Ena, Ina);                                               \
            /* pointwise-B + tail-B */                                         \
            const u64 g2b = ffma2(EIa, ninvt2, kinvt2);                        \
            const u64 h2b = ffma2(g2b, nS02, fmul2(EIa, cc2));                 \
            const u64 ba_b = ffma2(m2, pack2(Ena, Ena),                        \
                                   ffma2(p2, pack2(Ina, Ina), c02));           \
            float base_eb, argIb;                                              \
            unpk(ba_b, base_eb, argIb);                                        \
            const float sIb = rcpa(1.0f + ex2a(argIb));                        \
            const float argEb = connB + base_eb;                               \
            const float sEb = rcpa(1.0f + ex2a(argEb));                        \
            const u64 EIb = ffma2(g2b, pack2(sEb, sIb), h2b);                  \
            float Enb, Inb;                                                    \
            unpk(EIb, Enb, Inb);                                               \
            /* publish: {E_{S+1}, E_{S+2}} pair + output pair, 2 STS.64 */     \
            einter[(CUR) ^ 1][r] = pack2(Ena, Enb);                            \
            *reinterpret_cast<u64*>(                                           \
                &outbuf[((S) >> 5) & 1][r][(S) & (TILE - 1)]) =                \
                pack2(Ena - Ina, Enb - Inb);                                   \
            EI = EIb;                                                          \
        }                                                                      \
        __syncthreads();                                                       \
        if (wid == 3) {                                                        \
            FLUSH_STEP(S)                                                      \
            FLUSH_STEP((S) + 1)                                                \
        }                                                                      \
    }

    int s = 0;
    for (; s + 4 <= num_steps; s += 4) {
        BLOCK(0, s)
        BLOCK(1, s + 2)
    }
    if (s + 2 <= num_steps) {   // here s % 4 == 0 => block parity 0
        BLOCK(0, s)
        s += 2;
    }
    if (s < num_steps) {        // odd leftover step (s even = 2k)
        const int cur = (s >> 1) & 1;
        if (r < NN) {
            const u64 g2 = ffma2(EI, ninvt2, kinvt2);
            const u64 h2 = ffma2(g2, nS02, fmul2(EI, cc2));
            float Ec, Ic;
            unpk(EI, Ec, Ic);
            const u64 ba = ffma2(m2, pack2(Ec, Ec),
                                 ffma2(p2, pack2(Ic, Ic), c02));
            float base_e, argI;
            unpk(ba, base_e, argI);
            const float sIv = rcpa(1.0f + ex2a(argI));
            const ulonglong2* eb =
                reinterpret_cast<const ulonglong2*>(einter[cur]);
            u64 a0 = pack2(base_e, 0.0f);
            u64 a1 = 0ull, a2 = 0ull, a3 = 0ull;
            #pragma unroll
            for (int j = 0; j < 34; j++) {
                ulonglong2 e = eb[j];
                if (j & 1) {
                    a2 = ffma2(cw[2 * j],     e.x, a2);
                    a3 = ffma2(cw[2 * j + 1], e.y, a3);
                } else {
                    a0 = ffma2(cw[2 * j],     e.x, a0);
                    a1 = ffma2(cw[2 * j + 1], e.y, a1);
                }
            }
            u64 sv = fadd2(fadd2(a0, a2), fadd2(a1, a3));
            float argE, dummy;
            unpk(sv, argE, dummy);        // A-half only (B-half unused)
            const float sEv = rcpa(1.0f + ex2a(argE));
            const u64 EIn = ffma2(g2, pack2(sEv, sIv), h2);
            float En, In;
            unpk(EIn, En, In);
            outbuf[(s >> 5) & 1][r][s & (TILE - 1)] = En - In;
        }
        __syncthreads();
        s++;
    }
#undef BLOCK
#undef FLUSH_STEP

    // Epilogue: flush tiles the in-loop warp-3 flush couldn't cover.
    int start;
    if (num_steps < 36) start = 0;
    else                start = (((num_steps - 36) >> 5) << 5) + 32;
    for (int tb = start; tb < num_steps; tb += 32) {
        const int ftile = (tb >> 5) & 1;
        const int cnt   = num_steps - tb < 32 ? num_steps - tb : 32;
        for (int row = wid; row < NN; row += 4)
            if (lane < cnt)
                out[row * num_steps + tb + lane] = outbuf[ftile][row][lane];
    }
}

extern "C" void kernel_launch(void* const* d_in, const int* in_sizes, int n_in,
                              void* d_out, int out_size)
{
    const float* params = (const float*)d_in[0];
    const float* Cjk    = (const float*)d_in[1];
    const float* y0     = (const float*)d_in[2];
    // d_in[3] = Djk: unused by the reference computation.
    float* out = (float*)d_out;
    const int num_steps = out_size / NN;   // out is (N=68, num_steps)
    nmm_kernel<<<1, TPB>>>(params, Cjk, y0, out, num_steps);
}

// round 9
// speedup vs baseline: 1.0181x; 1.0181x over previous
#include <cuda_runtime.h>
#include <math.h>

#define NN    68
#define TPB   128
#define TILE  32

typedef unsigned long long u64;

// Packed f32x2 ops (Blackwell) — only reachable via PTX.
__device__ __forceinline__ u64 ffma2(u64 a, u64 b, u64 c) {
    u64 d;
    asm("fma.rn.f32x2 %0, %1, %2, %3;" : "=l"(d) : "l"(a), "l"(b), "l"(c));
    return d;
}
__device__ __forceinline__ u64 fadd2(u64 a, u64 b) {
    u64 d;
    asm("add.rn.f32x2 %0, %1, %2;" : "=l"(d) : "l"(a), "l"(b));
    return d;
}
__device__ __forceinline__ u64 fmul2(u64 a, u64 b) {
    u64 d;
    asm("mul.rn.f32x2 %0, %1, %2;" : "=l"(d) : "l"(a), "l"(b));
    return d;
}
__device__ __forceinline__ void unpk(u64 v, float &x, float &y) {
    asm("mov.b64 {%0, %1}, %2;" : "=f"(x), "=f"(y) : "l"(v));
}
__device__ __forceinline__ u64 pack2(float x, float y) {
    u64 v;
    asm("mov.b64 %0, {%1, %2};" : "=l"(v) : "f"(x), "f"(y));
    return v;
}
// MUFU fast paths (~1e-7 rel err; validated 1.31e-6 final over 200k steps).
__device__ __forceinline__ float ex2a(float x) {
    float y; asm("ex2.approx.f32 %0, %1;" : "=f"(y) : "f"(x)); return y;
}
__device__ __forceinline__ float rcpa(float x) {
    float y; asm("rcp.approx.f32 %0, %1;" : "=f"(y) : "f"(x)); return y;
}

__global__ __launch_bounds__(TPB, 1)
void nmm_kernel(const float* __restrict__ params,
                const float* __restrict__ C,
                const float* __restrict__ y0,
                float* __restrict__ out,
                int num_steps)
{
    // 4-slot ring: E_t lives in ebuf[t & 3]. Block k (steps 2k, 2k+1) reads
    // E_{2k-1} (slot (P+3)&3) and E_{2k} (slot P); writes E_{2k+1}, E_{2k+2}
    // into (P+1)&3, (P+2)&3. One barrier per block orders all crossings.
    __shared__ __align__(16) float ebuf[4][72];
    // Ping-pong output staging; rows padded to 34 floats => 8B-aligned
    // STS.64 pair stores; flush reads stay row-contiguous (conflict-free).
    __shared__ __align__(16) float outbuf[2][NN][TILE + 2];

    const int tid  = threadIdx.x;
    const int lane = tid & 31;
    const int wid  = tid >> 5;
    const int r    = tid;                 // row owned by this thread (r < 68)

    const float tau_e = params[0], tau_i = params[1];
    const float c1 = params[2], c2 = params[3], c3 = params[4], c4 = params[5];
    const float c5 = params[6], Pp = params[7], kE = params[8], kI = params[9];
    const float inv_te = 1.0f / tau_e;
    const float inv_ti = 1.0f / tau_i;

    const float LOG2E = 1.4426950408889634f;
    const float AE = 1.3f, THR_E = 4.0f;
    const float AI = 2.0f, THR_I = 3.7f;
    const float aeL = AE * LOG2E;
    const float aiL = AI * LOG2E;
    const float S0E = 1.0f / (1.0f + expf(AE * THR_E));
    const float S0I = 1.0f / (1.0f + expf(AI * THR_I));
    const float kconn = -aeL * c5;        // folded into crow below

    // Packed constants for {E, I}-lane pointwise math (validated in R8).
    const u64 kinvt2 = pack2(kE * inv_te, kI * inv_ti);
    const u64 ninvt2 = pack2(-inv_te, -inv_ti);
    const u64 cc2    = pack2(1.0f - inv_te, 1.0f - inv_ti);
    const u64 nS02   = pack2(-S0E, -S0I);
    const u64 m2     = pack2(-aeL * c1, -aiL * c3);   // {mEc1, mIc3}
    const u64 p2     = pack2( aeL * c2,  aiL * c4);   // {pEc2, pIc4}
    const u64 c02    = pack2(aeL * (THR_E - Pp), aiL * THR_I);

    u64 EI = 0ull;                        // {E, I} state for this row
    u64 crow[34];                         // kconn * C[r,:], packed f32x2

    if (r < NN) {
        const float E0 = y0[r];
        EI = pack2(E0, y0[NN + r]);
        ebuf[3][r] = E0;                  // E_{-1} := E_0 (reference carry)
        ebuf[0][r] = E0;                  // E_0
        const ulonglong2* cp = reinterpret_cast<const ulonglong2*>(C + r * NN);
        const u64 k2 = pack2(kconn, kconn);
        #pragma unroll
        for (int j = 0; j < 17; j++) {
            ulonglong2 c = cp[j];
            crow[2 * j]     = fmul2(c.x, k2);
            crow[2 * j + 1] = fmul2(c.y, k2);
        }
    }
    __syncthreads();

    // Warp-3 flush of one step's column window (17 rows x 4 windows/tile).
#define FLUSH_STEP(X)                                                          \
    {                                                                          \
        const int fk = (X) & 31;                                               \
        if (fk < 4 && (X) >= 32) {                                             \
            const int fb    = ((X) >> 5) - 1;                                  \
            const int ftile = fb & 1;                                          \
            const int fbase = fb << 5;                                         \
            _Pragma("unroll")                                                  \
            for (int i = 0; i < 17; i++) {                                     \
                const int row = fk * 17 + i;                                   \
                out[row * num_steps + fbase + lane] = outbuf[ftile][row][lane];\
            }                                                                  \
        }                                                                      \
    }

    // ---- one block = 2 Euler steps (S even), ONE barrier ----
    // PAR = S % 4 (compile-time 0 or 2 in the main loop).
    // Ordering: mvA -> reduce-A -> launch tail-A MUFU -> mvB (issue stream
    // fills tail-A's MUFU shadow) -> finish A -> pointwise/tail-B.
#define BLOCK(PAR, S)                                                          \
    {                                                                          \
        if (r < NN) {                                                          \
            /* pointwise-A (packed {E,I}) from state at iteration S */         \
            const u64 g2a = ffma2(EI, ninvt2, kinvt2);                         \
            const u64 h2a = ffma2(g2a, nS02, fmul2(EI, cc2));                  \
            float Ea, Ia;                                                      \
            unpk(EI, Ea, Ia);                                                  \
            const u64 ba_a = ffma2(m2, pack2(Ea, Ea),                          \
                                   ffma2(p2, pack2(Ia, Ia), c02));             \
            float base_ea, argIa;                                              \
            unpk(ba_a, base_ea, argIa);                                        \
            const float sIa = rcpa(1.0f + ex2a(argIa));                       \
            /* matvec-A over E_{S-1} (summation order = validated R7) */       \
            const ulonglong2* ea =                                             \
                reinterpret_cast<const ulonglong2*>(ebuf[((PAR) + 3) & 3]);    \
            u64 a0 = pack2(base_ea, 0.0f);                                     \
            u64 a1 = 0ull, a2 = 0ull, a3 = 0ull;                               \
            _Pragma("unroll")                                                  \
            for (int j = 0; j < 17; j++) {                                     \
                ulonglong2 e = ea[j];                                          \
                if (j & 1) {                                                   \
                    a2 = ffma2(crow[2 * j],     e.x, a2);                      \
                    a3 = ffma2(crow[2 * j + 1], e.y, a3);                      \
                } else {                                                       \
                    a0 = ffma2(crow[2 * j],     e.x, a0);                      \
                    a1 = ffma2(crow[2 * j + 1], e.y, a1);                      \
                }                                                              \
            }                                                                  \
            /* reduce-A and LAUNCH tail-A's MUFU chain now */                  \
            u64 sv = fadd2(fadd2(a0, a1), fadd2(a2, a3));                      \
            float sx, sy;                                                      \
            unpk(sv, sx, sy);                                                  \
            const float argEa = sx + sy;                                       \
            const float sEa   = rcpa(1.0f + ex2a(argEa));                      \
            /* matvec-B over E_S — independent; its FFMA2 issue stream   */    \
            /* overlaps tail-A's EX2/RCP latency.                        */    \
            const ulonglong2* eb2 =                                            \
                reinterpret_cast<const ulonglong2*>(ebuf[(PAR)]);              \
            u64 b0 = 0ull, b1 = 0ull, b2 = 0ull, b3 = 0ull;                    \
            _Pragma("unroll")                                                  \
            for (int j = 0; j < 17; j++) {                                     \
                ulonglong2 e = eb2[j];                                         \
                if (j & 1) {                                                   \
                    b2 = ffma2(crow[2 * j],     e.x, b2);                      \
                    b3 = ffma2(crow[2 * j + 1], e.y, b3);                      \
                } else {                                                       \
                    b0 = ffma2(crow[2 * j],     e.x, b0);                      \
                    b1 = ffma2(crow[2 * j + 1], e.y, b1);                      \
                }                                                              \
            }                                                                  \
            /* finish A: packed state update (validated R8 math) */            \
            const u64 EIa = ffma2(g2a, pack2(sEa, sIa), h2a);                  \
            float Ena, Ina;                                                    \
            unpk(EIa, Ena, Ina);                                               \
            ebuf[((PAR) + 1) & 3][r] = Ena;        /* publish E_{S+1} */       \
            /* pointwise-B + tail-B */                                         \
            const u64 g2b = ffma2(EIa, ninvt2, kinvt2);                        \
            const u64 h2b = ffma2(g2b, nS02, fmul2(EIa, cc2));                 \
            const u64 ba_b = ffma2(m2, pack2(Ena, Ena),                        \
                                   ffma2(p2, pack2(Ina, Ina), c02));           \
            float base_eb, argIb;                                              \
            unpk(ba_b, base_eb, argIb);                                        \
            const float sIb = rcpa(1.0f + ex2a(argIb));                        \
            u64 tv = fadd2(fadd2(b0, b1), fadd2(b2, b3));                      \
            float tx, ty;                                                      \
            unpk(tv, tx, ty);                                                  \
            const float argEb = (tx + ty) + base_eb;                           \
            const float sEb   = rcpa(1.0f + ex2a(argEb));                      \
            const u64 EIb = ffma2(g2b, pack2(sEb, sIb), h2b);                  \
            float Enb, Inb;                                                    \
            unpk(EIb, Enb, Inb);                                               \
            ebuf[((PAR) + 2) & 3][r] = Enb;        /* publish E_{S+2} */       \
            *reinterpret_cast<u64*>(                                           \
                &outbuf[((S) >> 5) & 1][r][(S) & (TILE - 1)]) =                \
                pack2(Ena - Ina, Enb - Inb);                                   \
            EI = EIb;                                                          \
        }                                                                      \
        __syncthreads();                                                       \
        if (wid == 3) {                                                        \
            FLUSH_STEP(S)                                                      \
            FLUSH_STEP((S) + 1)                                                \
        }                                                                      \
    }

    int s = 0;
    for (; s + 4 <= num_steps; s += 4) {
        BLOCK(0, s)
        BLOCK(2, s + 2)
    }
    if (s + 2 <= num_steps) {   // here s % 4 == 0
        BLOCK(0, s)
        s += 2;
    }
    if (s < num_steps) {        // odd leftover step (generic, runtime slot)
        if (r < NN) {
            const u64 g2 = ffma2(EI, ninvt2, kinvt2);
            const u64 h2 = ffma2(g2, nS02, fmul2(EI, cc2));
            float Ec, Ic;
            unpk(EI, Ec, Ic);
            const u64 ba = ffma2(m2, pack2(Ec, Ec),
                                 ffma2(p2, pack2(Ic, Ic), c02));
            float base_e, argI;
            unpk(ba, base_e, argI);
            const float sIv = rcpa(1.0f + ex2a(argI));
            const ulonglong2* ea =
                reinterpret_cast<const ulonglong2*>(ebuf[(s + 3) & 3]);
            u64 a0 = pack2(base_e, 0.0f);
            u64 a1 = 0ull, a2 = 0ull, a3 = 0ull;
            #pragma unroll
            for (int j = 0; j < 17; j++) {
                ulonglong2 e = ea[j];
                if (j & 1) {
                    a2 = ffma2(crow[2 * j],     e.x, a2);
                    a3 = ffma2(crow[2 * j + 1], e.y, a3);
                } else {
                    a0 = ffma2(crow[2 * j],     e.x, a0);
                    a1 = ffma2(crow[2 * j + 1], e.y, a1);
                }
            }
            u64 sv = fadd2(fadd2(a0, a1), fadd2(a2, a3));
            float sx, sy;
            unpk(sv, sx, sy);
            const float argE = sx + sy;
            const float sEv  = rcpa(1.0f + ex2a(argE));
            const u64 EIn = ffma2(g2, pack2(sEv, sIv), h2);
            float En, In;
            unpk(EIn, En, In);
            outbuf[(s >> 5) & 1][r][s & (TILE - 1)] = En - In;
        }
        __syncthreads();
        s++;
    }
#undef BLOCK
#undef FLUSH_STEP

    // Epilogue: flush tiles the in-loop warp-3 flush couldn't cover
    // (last complete tile whose flush window fell off the end + partial tile).
    int start;
    if (num_steps < 36) start = 0;
    else                start = (((num_steps - 36) >> 5) << 5) + 32;
    for (int tb = start; tb < num_steps; tb += 32) {
        const int ftile = (tb >> 5) & 1;
        const int cnt   = num_steps - tb < 32 ? num_steps - tb : 32;
        for (int row = wid; row < NN; row += 4)
            if (lane < cnt)
                out[row * num_steps + tb + lane] = outbuf[ftile][row][lane];
    }
}

extern "C" void kernel_launch(void* const* d_in, const int* in_sizes, int n_in,
                              void* d_out, int out_size)
{
    const float* params = (const float*)d_in[0];
    const float* Cjk    = (const float*)d_in[1];
    const float* y0     = (const float*)d_in[2];
    // d_in[3] = Djk: unused by the reference computation.
    float* out = (float*)d_out;
    const int num_steps = out_size / NN;   // out is (N=68, num_steps)
    nmm_kernel<<<1, TPB>>>(params, Cjk, y0, out, num_steps);
}